// round 17
// baseline (speedup 1.0000x reference)
#include <cuda_runtime.h>
#include <cuda_bf16.h>
#include <cstddef>
#include <cstdint>

// Problem constants (B=4096, n=512, m=1024)
#define Bsz 4096
#define Nn  512
#define Mm  1024
#define STEPC 0.01f
#define INVSTEP 100.0f
#define TOLV 1e-5f

// ---- generic tc_gemm tile config (TM=128, TN=256) ----
#define TM 128
#define TN 256
#define TILEA_B 16384          // 128x64 bf16 tile bytes
#define TILEB_B 32768          // 256x64 bf16 tile bytes
#define OFF_ALO 16384
#define OFF_BHI 32768
#define OFF_BLO 65536
#define STG_SZ  98304          // 96 KB per stage
#define DSMEM   (2 * STG_SZ + 1024)

// ---- PGD tile config (TM=256, TN=128): traffic-optimal ----
#define OFF3_A1  16384
#define OFF3_BHI 32768
#define OFF3_BLO 49152
#define STG3_SZ  65536         // 64 KB per stage
#define DSMEM3   (2 * STG3_SZ + 1024)

#if defined(__CUDA_ARCH__) && defined(__CUDA_ARCH_FEAT_SM103_ALL)
#define HAS_TCGEN05 1
#else
#define HAS_TCGEN05 0
#endif

// ---------------- device scratch (allocation-free) ----------------
__device__ __align__(128) float g_c[(size_t)Bsz * Mm];
__device__ __align__(128) float g_msk[(size_t)Bsz * Mm];
__device__ __align__(128) float g_act[(size_t)Bsz * Mm];
__device__ __align__(128) float g_qdiag[Mm];                // diag(Q') fp32
__device__ __align__(128) __nv_bfloat16 g_AAi_h[Mm * Nn];   // A as A-image [8][8]
__device__ __align__(128) __nv_bfloat16 g_AAi_l[Mm * Nn];
__device__ __align__(128) __nv_bfloat16 g_ABi_h[Mm * Nn];   // A as B-image [4][8]
__device__ __align__(128) __nv_bfloat16 g_ABi_l[Mm * Nn];
__device__ __align__(128) __nv_bfloat16 g_ATi_h[Nn * Mm];   // A^T as B-image [2][16]
__device__ __align__(128) __nv_bfloat16 g_ATi_l[Nn * Mm];
__device__ __align__(128) __nv_bfloat16 g_xu_h[(size_t)Bsz * Nn];
__device__ __align__(128) __nv_bfloat16 g_xu_l[(size_t)Bsz * Nn];
__device__ __align__(128) __nv_bfloat16 g_u_h[(size_t)Bsz * Nn];
__device__ __align__(128) __nv_bfloat16 g_u_l[(size_t)Bsz * Nn];
__device__ __align__(128) __nv_bfloat16 g_z_h[(size_t)Bsz * Nn];
__device__ __align__(128) __nv_bfloat16 g_z_l[(size_t)Bsz * Nn];
// Q' = Q - (1/step) I as 128-row B-tiles: [8 nb][16 ch][128x64, 16 KB]
__device__ __align__(128) __nv_bfloat16 g_Qhi[Mm * Mm];
__device__ __align__(128) __nv_bfloat16 g_Qlo[Mm * Mm];
__device__ __align__(128) __nv_bfloat16 g_lAhi[(size_t)Bsz * Mm]; // lam A-images [32][16]
__device__ __align__(128) __nv_bfloat16 g_lAlo[(size_t)Bsz * Mm];
__device__ __align__(128) __nv_bfloat16 g_lBhi[(size_t)Bsz * Mm];
__device__ __align__(128) __nv_bfloat16 g_lBlo[(size_t)Bsz * Mm];

// ---------------- helpers ----------------
__device__ __forceinline__ uint32_t s2u(const void* p) {
    uint32_t a;
    asm("{ .reg .u64 t; cvta.to.shared.u64 t, %1; cvt.u32.u64 %0, t; }"
        : "=r"(a) : "l"(p));
    return a;
}
__device__ __forceinline__ uint32_t swz(uint32_t off) {
    return off ^ ((off >> 3) & 0x70);
}
__device__ __forceinline__ void mbar_init(uint32_t a, uint32_t cnt) {
    asm volatile("mbarrier.init.shared.b64 [%0], %1;" :: "r"(a), "r"(cnt) : "memory");
}
__device__ __forceinline__ void mbar_arrive_tx(uint32_t a, uint32_t bytes) {
    asm volatile("mbarrier.arrive.expect_tx.shared.b64 _, [%0], %1;"
                 :: "r"(a), "r"(bytes) : "memory");
}
__device__ __forceinline__ void mbar_tx_only(uint32_t a, uint32_t bytes) {
    asm volatile("mbarrier.expect_tx.shared.b64 [%0], %1;"
                 :: "r"(a), "r"(bytes) : "memory");
}
__device__ __forceinline__ void mbar_wait(uint32_t a, uint32_t phase) {
    uint32_t done = 0;
    while (!done) {
        asm volatile(
            "{ .reg .pred p; mbarrier.try_wait.parity.shared.b64 p, [%1], %2; "
            "selp.b32 %0, 1, 0, p; }"
            : "=r"(done) : "r"(a), "r"(phase) : "memory");
    }
}
__device__ __forceinline__ void bulk_g2s(uint32_t dst, const void* src,
                                         uint32_t bytes, uint32_t mbar) {
    asm volatile(
        "cp.async.bulk.shared::cluster.global.mbarrier::complete_tx::bytes "
        "[%0], [%1], %2, [%3];"
        :: "r"(dst), "l"(src), "r"(bytes), "r"(mbar) : "memory");
}
__device__ __forceinline__ uint64_t mkdesc(uint32_t addr) {
    return ((uint64_t)2 << 61) | ((uint64_t)1 << 46) | ((uint64_t)64 << 32)
         | ((uint64_t)1 << 16) | ((addr >> 4) & 0x3FFF);
}
#define GEMM_IDESC ((1u<<4) | (1u<<7) | (1u<<10) | ((TN/8)<<17) | ((128/16)<<24))
#define PGD_IDESC  ((1u<<4) | (1u<<7) | (1u<<10) | ((128/8)<<17) | ((128/16)<<24))
#define GDC_WAIT()   asm volatile("griddepcontrol.wait;" ::: "memory")
#define GDC_LAUNCH() asm volatile("griddepcontrol.launch_dependents;" ::: "memory")

__device__ __forceinline__ float bfbits2f(uint16_t u) {
    __nv_bfloat16_raw r; r.x = u;
    return __bfloat162float(__nv_bfloat16(r));
}
__device__ __forceinline__ uint16_t f2bfbits(float f) {
    __nv_bfloat16 h = __float2bfloat16(f);
    __nv_bfloat16_raw r = (__nv_bfloat16_raw)h;
    return r.x;
}

#if HAS_TCGEN05
__device__ __forceinline__ void mma_f16_ss(uint32_t d, uint64_t a, uint64_t b,
                                           uint32_t idesc, uint32_t en) {
    asm volatile(
        "{\n\t.reg .pred p;\n\tsetp.ne.u32 p, %5, 0;\n\t"
        "tcgen05.mma.cta_group::1.kind::f16 [%0], %1, %2, %3, {%4,%4,%4,%4}, p;\n\t}"
        :: "r"(d), "l"(a), "l"(b), "r"(idesc), "r"(0u), "r"(en) : "memory");
}
__device__ __forceinline__ void tc_commit(uint32_t mbar) {
    asm volatile(
        "tcgen05.commit.cta_group::1.mbarrier::arrive::one.shared::cluster.b64 [%0];"
        :: "r"(mbar) : "memory");
}
#define TC_ALLOC(sres, n) \
    asm volatile("tcgen05.alloc.cta_group::1.sync.aligned.shared::cta.b32 [%0], %1;" \
                 :: "r"(sres), "r"((uint32_t)(n)) : "memory")
#define TC_RELINQ() \
    asm volatile("tcgen05.relinquish_alloc_permit.cta_group::1.sync.aligned;")
#define TC_DEALLOC(t, n) \
    asm volatile("tcgen05.dealloc.cta_group::1.sync.aligned.b32 %0, %1;" :: "r"(t), "r"((uint32_t)(n)))
#define TC_FENCE_AFTER()  asm volatile("tcgen05.fence::after_thread_sync;" ::: "memory")
#define TC_WAIT_LD()      asm volatile("tcgen05.wait::ld.sync.aligned;" ::: "memory")
#define LDTM_X32(r, a) \
    asm volatile( \
        "tcgen05.ld.sync.aligned.32x32b.x32.b32 " \
        "{%0,%1,%2,%3,%4,%5,%6,%7,%8,%9,%10,%11,%12,%13,%14,%15," \
        "%16,%17,%18,%19,%20,%21,%22,%23,%24,%25,%26,%27,%28,%29,%30,%31}, [%32];" \
        : "=r"((r)[0]),"=r"((r)[1]),"=r"((r)[2]),"=r"((r)[3]), \
          "=r"((r)[4]),"=r"((r)[5]),"=r"((r)[6]),"=r"((r)[7]), \
          "=r"((r)[8]),"=r"((r)[9]),"=r"((r)[10]),"=r"((r)[11]), \
          "=r"((r)[12]),"=r"((r)[13]),"=r"((r)[14]),"=r"((r)[15]), \
          "=r"((r)[16]),"=r"((r)[17]),"=r"((r)[18]),"=r"((r)[19]), \
          "=r"((r)[20]),"=r"((r)[21]),"=r"((r)[22]),"=r"((r)[23]), \
          "=r"((r)[24]),"=r"((r)[25]),"=r"((r)[26]),"=r"((r)[27]), \
          "=r"((r)[28]),"=r"((r)[29]),"=r"((r)[30]),"=r"((r)[31]) \
        : "r"(a))
#endif  // HAS_TCGEN05

// ---------------------------------------------------------------------------
// PGD iteration, TM=256 x TN=128 tile (two 128x128 TMEM accumulators):
//   acc2 = lam_hi @ (Q'hi + Q'lo)      (2 products per D tile)
//   acc  = acc2 + lam_lo[r,c] * qd[c]  (diagonal compensation)
//   lam_new = relu(step * (c - acc))   [* act]
//   Stage: A0,A1 (two 128-row lam tiles) + Q'hi,Q'lo (128-row tiles), 64 KB.
//   PDL + warp-specialized producer (tid 32) / consumer (tid 0).
// ---------------------------------------------------------------------------
__global__ void __launch_bounds__(256, 1) pgd_pdl(
    const __nv_bfloat16* __restrict__ Ahi, const __nv_bfloat16* __restrict__ Alo,
    const __nv_bfloat16* __restrict__ Bhi, const __nv_bfloat16* __restrict__ Blo,
    const float* __restrict__ cc, const float* __restrict__ act,
    const float* __restrict__ qd,
    __nv_bfloat16* __restrict__ ohi, __nv_bfloat16* __restrict__ olo,
    int masked)
{
#if HAS_TCGEN05
    extern __shared__ char draw[];
    const uint32_t dsm = (s2u(draw) + 1023u) & ~1023u;

    __shared__ uint32_t s_tmem;
    __shared__ __align__(8) uint64_t s_bar[5];

    const int tid  = threadIdx.x;
    const int wid  = tid >> 5;
    const int lane = tid & 31;
    const int bm2  = blockIdx.y;          // 256-row block (0..15)
    const int bn   = blockIdx.x;          // 128-col block (0..7)
    const int bn0  = bn * 128;

    const uint32_t f0 = s2u(&s_bar[0]);
    const uint32_t f1 = s2u(&s_bar[1]);
    const uint32_t e0 = s2u(&s_bar[2]);
    const uint32_t e1 = s2u(&s_bar[3]);
    const uint32_t db = s2u(&s_bar[4]);

    if (wid == 0) TC_ALLOC(s2u(&s_tmem), 256);
    if (tid == 0) {
        mbar_init(f0, 1); mbar_init(f1, 1);
        mbar_init(e0, 1); mbar_init(e1, 1);
        mbar_init(db, 1);
    }
    __syncthreads();
    uint32_t tmem;
    asm volatile("ld.shared.b32 %0, [%1];" : "=r"(tmem) : "r"(s2u(&s_tmem)));

    const char* aH0 = (const char*)Ahi + (size_t)(bm2 * 2)     * 16 * TILEA_B;
    const char* aH1 = (const char*)Ahi + (size_t)(bm2 * 2 + 1) * 16 * TILEA_B;
    const char* bH  = (const char*)Bhi + (size_t)bn * 16 * TILEA_B;
    const char* bL  = (const char*)Blo + (size_t)bn * 16 * TILEA_B;

    // ---- producer: early Q loads (pre-wait; Q' is iteration-invariant) ----
    if (tid == 32) {
#pragma unroll
        for (int ch = 0; ch < 2; ch++) {
            const uint32_t fb = ch ? f1 : f0;
            const uint32_t st = dsm + (uint32_t)ch * STG3_SZ;
            mbar_tx_only(fb, 2 * TILEA_B);
            bulk_g2s(st + OFF3_BHI, bH + (size_t)ch * TILEA_B, TILEA_B, fb);
            bulk_g2s(st + OFF3_BLO, bL + (size_t)ch * TILEA_B, TILEA_B, fb);
        }
    }

    // all threads: wait for predecessor's lam/c/act writes
    GDC_WAIT();

    // ---- producer: lam_hi loads for stages 0,1 then stage refills ----
    if (tid == 32) {
#pragma unroll
        for (int ch = 0; ch < 2; ch++) {
            const uint32_t fb = ch ? f1 : f0;
            const uint32_t st = dsm + (uint32_t)ch * STG3_SZ;
            mbar_arrive_tx(fb, 2 * TILEA_B);
            bulk_g2s(st,           aH0 + (size_t)ch * TILEA_B, TILEA_B, fb);
            bulk_g2s(st + OFF3_A1, aH1 + (size_t)ch * TILEA_B, TILEA_B, fb);
        }
        uint32_t phe[2] = {0, 0};
#pragma unroll 1
        for (int nx = 2; nx < 16; nx++) {
            const int s = nx & 1;
            mbar_wait(s ? e1 : e0, phe[s]); phe[s] ^= 1;
            const uint32_t fb = s ? f1 : f0;
            const uint32_t st = dsm + (uint32_t)s * STG3_SZ;
            mbar_arrive_tx(fb, (uint32_t)STG3_SZ);
            bulk_g2s(st,            aH0 + (size_t)nx * TILEA_B, TILEA_B, fb);
            bulk_g2s(st + OFF3_A1,  aH1 + (size_t)nx * TILEA_B, TILEA_B, fb);
            bulk_g2s(st + OFF3_BHI, bH  + (size_t)nx * TILEA_B, TILEA_B, fb);
            bulk_g2s(st + OFF3_BLO, bL  + (size_t)nx * TILEA_B, TILEA_B, fb);
        }
    }

    // ---- consumer: MMA issue (2 products x 2 D tiles per k-step) ----
    if (tid == 0) {
        uint32_t phf[2] = {0, 0};
#pragma unroll 1
        for (int ch = 0; ch < 16; ch++) {
            const int s = ch & 1;
            mbar_wait(s ? f1 : f0, phf[s]); phf[s] ^= 1;

            const uint32_t st = dsm + (uint32_t)s * STG3_SZ;
            const uint64_t da0 = mkdesc(st);
            const uint64_t da1 = mkdesc(st + OFF3_A1);
            const uint64_t dbh = mkdesc(st + OFF3_BHI);
            const uint64_t dbl = mkdesc(st + OFF3_BLO);
#pragma unroll
            for (int ks = 0; ks < 4; ks++) {
                const uint32_t en = (ch == 0 && ks == 0) ? 0u : 1u;
                mma_f16_ss(tmem,       da0 + ks * 2, dbh + ks * 2, PGD_IDESC, en);
                mma_f16_ss(tmem,       da0 + ks * 2, dbl + ks * 2, PGD_IDESC, 1u);
                mma_f16_ss(tmem + 128, da1 + ks * 2, dbh + ks * 2, PGD_IDESC, en);
                mma_f16_ss(tmem + 128, da1 + ks * 2, dbl + ks * 2, PGD_IDESC, 1u);
            }
            tc_commit(s ? e1 : e0);
        }
        tc_commit(db);
    }

    mbar_wait(db, 0);
    TC_FENCE_AFTER();

    // ---- fused epilogue: warps 0-3 -> D0 (rows +0), warps 4-7 -> D1 (+128)
    const int tileD = wid >> 2;            // 0 or 1
    const int sp    = wid & 3;
    const int lr    = sp * 32 + lane;      // local row 0..127 within tile
    const int bmA   = bm2 * 2 + tileD;     // lam 128-row tile index
    const int r     = bmA * 128 + lr;      // global row

#pragma unroll 1
    for (int cb = 0; cb < 128; cb += 32) {
        uint32_t dreg[32];
        LDTM_X32(dreg, tmem + tileD * 128 + cb);

        const int gch  = (bn0 + cb) >> 6;
        const int lc0  = cb & 63;
        const size_t tb = ((size_t)(bmA * 16 + gch)) * TILEA_B;
        const size_t blin = (size_t)r * Mm + bn0 + cb;

        float4   cv[8];
        float4   qv[8];
        uint64_t l4[8];
        float4   av[8];
        uint32_t boff[8];
#pragma unroll
        for (int g = 0; g < 8; g++) {
            const int j0 = g * 4;
            boff[g] = swz((uint32_t)(lr * 128 + (lc0 + j0) * 2));
            cv[g] = *(const float4*)&cc[blin + j0];
            qv[g] = *(const float4*)&qd[bn0 + cb + j0];
            l4[g] = *(const uint64_t*)((const char*)Alo + tb + boff[g]);
            if (masked) av[g] = *(const float4*)&act[blin + j0];
        }

        TC_WAIT_LD();

#pragma unroll
        for (int g = 0; g < 8; g++) {
            const int j0 = g * 4;
            const float* cvp = (const float*)&cv[g];
            const float* qvp = (const float*)&qv[g];
            const float* avp = (const float*)&av[g];
            uint16_t oh[4], ol[4];
#pragma unroll
            for (int k = 0; k < 4; k++) {
                float acc = __uint_as_float(dreg[j0 + k]);
                float lamlo = bfbits2f((uint16_t)(l4[g] >> (16 * k)));
                acc += lamlo * qvp[k];                 // diagonal compensation
                float v = fmaxf(STEPC * (cvp[k] - acc), 0.f);
                if (masked) v *= avp[k];
                uint16_t hb = f2bfbits(v);
                oh[k] = hb;
                ol[k] = f2bfbits(v - bfbits2f(hb));
            }
            *(uint64_t*)((char*)ohi + tb + boff[g]) =
                (uint64_t)oh[0] | ((uint64_t)oh[1] << 16)
                | ((uint64_t)oh[2] << 32) | ((uint64_t)oh[3] << 48);
            *(uint64_t*)((char*)olo + tb + boff[g]) =
                (uint64_t)ol[0] | ((uint64_t)ol[1] << 16)
                | ((uint64_t)ol[2] << 32) | ((uint64_t)ol[3] << 48);
        }
    }

    GDC_LAUNCH();

    __syncthreads();
    if (wid == 0) { TC_RELINQ(); TC_DEALLOC(tmem, 256); }
#endif  // HAS_TCGEN05
}

// epilogue variants (cg1 peripheral GEMMs)
enum { E_C = 0, E_ACT, E_MSK, E_Z, E_OUT, E_Q };

// ---------------------------------------------------------------------------
// Generic cg1 tcgen05 GEMM (3-product), fused epilogues, optional PDL early.
//   E_Q writes Q' = acc - (1/step) I as 128-row B-tiles + fp32 diag (o32).
// ---------------------------------------------------------------------------
template <int EPI>
__global__ void __launch_bounds__(256, 1) tc_gemm(
    const __nv_bfloat16* __restrict__ Ahi, const __nv_bfloat16* __restrict__ Alo,
    const __nv_bfloat16* __restrict__ Bhi, const __nv_bfloat16* __restrict__ Blo,
    int nch,
    const float* __restrict__ v1, const float* __restrict__ v2,
    float* __restrict__ o32,
    __nv_bfloat16* __restrict__ ohi, __nv_bfloat16* __restrict__ olo,
    int Ncols, int early)
{
#if HAS_TCGEN05
    extern __shared__ char draw[];
    const uint32_t dsm = (s2u(draw) + 1023u) & ~1023u;

    __shared__ uint32_t s_tmem;
    __shared__ __align__(8) uint64_t s_bar[5];

    const int tid  = threadIdx.x;
    const int wid  = tid >> 5;
    const int lane = tid & 31;
    const int bm0  = blockIdx.y * TM;
    const int bn0  = blockIdx.x * TN;

    const uint32_t f0 = s2u(&s_bar[0]);
    const uint32_t f1 = s2u(&s_bar[1]);
    const uint32_t e0 = s2u(&s_bar[2]);
    const uint32_t e1 = s2u(&s_bar[3]);
    const uint32_t db = s2u(&s_bar[4]);

    if (wid == 0) TC_ALLOC(s2u(&s_tmem), 256);
    if (tid == 0) {
        mbar_init(f0, 1); mbar_init(f1, 1);
        mbar_init(e0, 1); mbar_init(e1, 1);
        mbar_init(db, 1);
    }
    __syncthreads();
    uint32_t tmem;
    asm volatile("ld.shared.b32 %0, [%1];" : "=r"(tmem) : "r"(s2u(&s_tmem)));

    const int earlyA = early & 1, earlyB = early & 2;
    const char* aH = (const char*)Ahi + (size_t)blockIdx.y * nch * TILEA_B;
    const char* aL = (const char*)Alo + (size_t)blockIdx.y * nch * TILEA_B;
    const char* bH = (const char*)Bhi + (size_t)blockIdx.x * nch * TILEB_B;
    const char* bL = (const char*)Blo + (size_t)blockIdx.x * nch * TILEB_B;

    if (tid == 0 && earlyB) {
#pragma unroll
        for (int ch = 0; ch < 2; ch++) {
            const uint32_t fb = ch ? f1 : f0;
            const uint32_t st = dsm + (uint32_t)ch * STG_SZ;
            mbar_tx_only(fb, 2 * TILEB_B);
            bulk_g2s(st + OFF_BHI, bH + (size_t)ch * TILEB_B, TILEB_B, fb);
            bulk_g2s(st + OFF_BLO, bL + (size_t)ch * TILEB_B, TILEB_B, fb);
        }
    }
    if (tid == 0 && earlyA) {
#pragma unroll
        for (int ch = 0; ch < 2; ch++) {
            const uint32_t fb = ch ? f1 : f0;
            const uint32_t st = dsm + (uint32_t)ch * STG_SZ;
            mbar_arrive_tx(fb, earlyB ? 2 * TILEA_B : (uint32_t)STG_SZ);
            bulk_g2s(st,           aH + (size_t)ch * TILEA_B, TILEA_B, fb);
            bulk_g2s(st + OFF_ALO, aL + (size_t)ch * TILEA_B, TILEA_B, fb);
            if (!earlyB) {
                bulk_g2s(st + OFF_BHI, bH + (size_t)ch * TILEB_B, TILEB_B, fb);
                bulk_g2s(st + OFF_BLO, bL + (size_t)ch * TILEB_B, TILEB_B, fb);
            }
        }
    }
    if (!earlyA) {
        GDC_WAIT();
        if (tid == 0) {
#pragma unroll
            for (int ch = 0; ch < 2; ch++) {
                const uint32_t fb = ch ? f1 : f0;
                const uint32_t st = dsm + (uint32_t)ch * STG_SZ;
                mbar_arrive_tx(fb, earlyB ? 2 * TILEA_B : (uint32_t)STG_SZ);
                bulk_g2s(st,           aH + (size_t)ch * TILEA_B, TILEA_B, fb);
                bulk_g2s(st + OFF_ALO, aL + (size_t)ch * TILEA_B, TILEA_B, fb);
                if (!earlyB) {
                    bulk_g2s(st + OFF_BHI, bH + (size_t)ch * TILEB_B, TILEB_B, fb);
                    bulk_g2s(st + OFF_BLO, bL + (size_t)ch * TILEB_B, TILEB_B, fb);
                }
            }
        }
    }

    if (tid == 0) {
        uint32_t phf[2] = {0, 0}, phe[2] = {0, 0};
#pragma unroll 1
        for (int ch = 0; ch < nch; ch++) {
            const int s = ch & 1;
            mbar_wait(s ? f1 : f0, phf[s]); phf[s] ^= 1;

            const uint32_t st = dsm + (uint32_t)s * STG_SZ;
            const uint64_t dah = mkdesc(st);
            const uint64_t dal = mkdesc(st + OFF_ALO);
            const uint64_t dbh = mkdesc(st + OFF_BHI);
            const uint64_t dbl = mkdesc(st + OFF_BLO);
#pragma unroll
            for (int ks = 0; ks < 4; ks++) {
                mma_f16_ss(tmem, dah + ks * 2, dbh + ks * 2, GEMM_IDESC,
                           (ch == 0 && ks == 0) ? 0u : 1u);
                mma_f16_ss(tmem, dah + ks * 2, dbl + ks * 2, GEMM_IDESC, 1u);
                mma_f16_ss(tmem, dal + ks * 2, dbh + ks * 2, GEMM_IDESC, 1u);
            }
            tc_commit(s ? e1 : e0);

            if (ch + 2 < nch) {
                mbar_wait(s ? e1 : e0, phe[s]); phe[s] ^= 1;
                const int nx = ch + 2;
                const uint32_t fb = s ? f1 : f0;
                const uint32_t st2 = dsm + (uint32_t)s * STG_SZ;
                mbar_arrive_tx(fb, (uint32_t)STG_SZ);
                bulk_g2s(st2,           aH + (size_t)nx * TILEA_B, TILEA_B, fb);
                bulk_g2s(st2 + OFF_ALO, aL + (size_t)nx * TILEA_B, TILEA_B, fb);
                bulk_g2s(st2 + OFF_BHI, bH + (size_t)nx * TILEB_B, TILEB_B, fb);
                bulk_g2s(st2 + OFF_BLO, bL + (size_t)nx * TILEB_B, TILEB_B, fb);
            }
        }
        tc_commit(db);
    }

    mbar_wait(db, 0);
    if (earlyA) GDC_WAIT();   // chain ordering before epilogue reads (e.g. act)
    TC_FENCE_AFTER();

    const int sp   = wid & 3;
    const int half = wid >> 2;
    const int lr   = sp * 32 + lane;
    const int r    = bm0 + lr;
    const int nchO = Ncols >> 6;

#pragma unroll 1
    for (int cb = 0; cb < 128; cb += 32) {
        uint32_t dreg[32];
        LDTM_X32(dreg, tmem + half * 128 + cb);
        TC_WAIT_LD();

        const int coff = half * 128 + cb;
        const int gch  = (bn0 + coff) >> 6;
        const int lc0  = coff & 63;
        const size_t blin = (size_t)r * Ncols + bn0 + coff;
        const size_t tbA = ((size_t)(blockIdx.y * nchO + gch)) * TILEA_B;
        // E_Q: 128-row B-tiles (A-image geometry)
        const size_t tbQ = ((size_t)((r >> 7) * nchO + gch)) * TILEA_B;
        const int qrow = r & 127;

#pragma unroll
        for (int j0 = 0; j0 < 32; j0 += 4) {
            const uint32_t boffA = swz((uint32_t)(lr * 128 + (lc0 + j0) * 2));
            float res[4];
#pragma unroll
            for (int k = 0; k < 4; k++) res[k] = __uint_as_float(dreg[j0 + k]);

            if (EPI == E_C) {
                float4 bv = *(const float4*)&v1[bn0 + coff + j0];
                const float* bp = (const float*)&bv;
                uint16_t oh[4], ol[4];
                float cvv[4];
#pragma unroll
                for (int k = 0; k < 4; k++) {
                    float cv = res[k] - bp[k];
                    cvv[k] = cv;
                    float v = fmaxf(STEPC * cv, 0.f);
                    uint16_t hb = f2bfbits(v);
                    oh[k] = hb; ol[k] = f2bfbits(v - bfbits2f(hb));
                }
                *(float4*)&o32[blin + j0] = make_float4(cvv[0], cvv[1], cvv[2], cvv[3]);
                *(uint64_t*)((char*)ohi + tbA + boffA) =
                    (uint64_t)oh[0] | ((uint64_t)oh[1] << 16)
                    | ((uint64_t)oh[2] << 32) | ((uint64_t)oh[3] << 48);
                *(uint64_t*)((char*)olo + tbA + boffA) =
                    (uint64_t)ol[0] | ((uint64_t)ol[1] << 16)
                    | ((uint64_t)ol[2] << 32) | ((uint64_t)ol[3] << 48);
            } else if (EPI == E_ACT) {
                float4 bv = *(const float4*)&v1[bn0 + coff + j0];
                const float* bp = (const float*)&bv;
                float o[4];
#pragma unroll
                for (int k = 0; k < 4; k++)
                    o[k] = (res[k] >= bp[k] - TOLV) ? 1.f : 0.f;
                *(float4*)&o32[blin + j0] = make_float4(o[0], o[1], o[2], o[3]);
            } else if (EPI == E_MSK) {
                float4 avv = *(const float4*)&v1[blin + j0];
                const float* ap = (const float*)&avv;
                uint16_t oh[4], ol[4];
                float mm[4];
#pragma unroll
                for (int k = 0; k < 4; k++) {
                    float m = res[k] * ap[k];
                    mm[k] = m;
                    float v = fmaxf(STEPC * m, 0.f) * ap[k];
                    uint16_t hb = f2bfbits(v);
                    oh[k] = hb; ol[k] = f2bfbits(v - bfbits2f(hb));
                }
                *(float4*)&o32[blin + j0] = make_float4(mm[0], mm[1], mm[2], mm[3]);
                *(uint64_t*)((char*)ohi + tbA + boffA) =
                    (uint64_t)oh[0] | ((uint64_t)oh[1] << 16)
                    | ((uint64_t)oh[2] << 32) | ((uint64_t)oh[3] << 48);
                *(uint64_t*)((char*)olo + tbA + boffA) =
                    (uint64_t)ol[0] | ((uint64_t)ol[1] << 16)
                    | ((uint64_t)ol[2] << 32) | ((uint64_t)ol[3] << 48);
            } else if (EPI == E_Z) {
                float4 xv = *(const float4*)&v1[blin + j0];
                float4 uv = *(const float4*)&v2[blin + j0];
                const float* xp = (const float*)&xv;
                const float* up = (const float*)&uv;
                uint16_t oh[4], ol[4];
#pragma unroll
                for (int k = 0; k < 4; k++) {
                    float zv = xp[k] + up[k] - res[k];
                    uint16_t hb = f2bfbits(zv);
                    oh[k] = hb; ol[k] = f2bfbits(zv - bfbits2f(hb));
                }
                *(uint64_t*)((char*)ohi + tbA + boffA) =
                    (uint64_t)oh[0] | ((uint64_t)oh[1] << 16)
                    | ((uint64_t)oh[2] << 32) | ((uint64_t)oh[3] << 48);
                *(uint64_t*)((char*)olo + tbA + boffA) =
                    (uint64_t)ol[0] | ((uint64_t)ol[1] << 16)
                    | ((uint64_t)ol[2] << 32) | ((uint64_t)ol[3] << 48);
            } else if (EPI == E_OUT) {
                float4 uv = *(const float4*)&v1[blin + j0];
                const float* up = (const float*)&uv;
                float o[4];
#pragma unroll
                for (int k = 0; k < 4; k++) o[k] = up[k] - res[k];
                *(float4*)&o32[blin + j0] = make_float4(o[0], o[1], o[2], o[3]);
            } else if (EPI == E_Q) {
                const uint32_t boffQ = swz((uint32_t)(qrow * 128 + (lc0 + j0) * 2));
                uint16_t oh[4], ol[4];
#pragma unroll
                for (int k = 0; k < 4; k++) {
                    float qv = res[k];
                    if (r == bn0 + coff + j0 + k) {
                        qv -= INVSTEP;           // Q' = Q - (1/step) I
                        o32[r] = qv;             // fp32 diag vector
                    }
                    uint16_t hb = f2bfbits(qv);
                    oh[k] = hb; ol[k] = f2bfbits(qv - bfbits2f(hb));
                }
                *(uint64_t*)((char*)ohi + tbQ + boffQ) =
                    (uint64_t)oh[0] | ((uint64_t)oh[1] << 16)
                    | ((uint64_t)oh[2] << 32) | ((uint64_t)oh[3] << 48);
                *(uint64_t*)((char*)olo + tbQ + boffQ) =
                    (uint64_t)ol[0] | ((uint64_t)ol[1] << 16)
                    | ((uint64_t)ol[2] << 32) | ((uint64_t)ol[3] << 48);
            }
        }
    }

    GDC_LAUNCH();

    __syncthreads();
    if (wid == 0) { TC_RELINQ(); TC_DEALLOC(tmem, 256); }
#endif  // HAS_TCGEN05
}

// ---------------- prep kernels ----------------
__device__ __forceinline__ void img_store(__nv_bfloat16* hi, __nv_bfloat16* lo,
                                          size_t tb, uint32_t boff, float v)
{
    __nv_bfloat16 h = __float2bfloat16(v);
    *(__nv_bfloat16*)((char*)hi + tb + boff) = h;
    *(__nv_bfloat16*)((char*)lo + tb + boff) = __float2bfloat16(v - __bfloat162float(h));
}

__global__ void split_A_images(const float* __restrict__ A)
{
    int i = blockIdx.x * blockDim.x + threadIdx.x;
    if (i >= Mm * Nn) return;
    int r = i >> 9, k = i & 511;
    float v = A[i];
    int ch = k >> 6, lc = k & 63;
    {
        int bm = r >> 7, lrow = r & 127;
        size_t tb = ((size_t)(bm * 8 + ch)) * TILEA_B;
        img_store(g_AAi_h, g_AAi_l, tb, swz((uint32_t)(lrow * 128 + lc * 2)), v);
    }
    {
        int nb = r >> 8, brow = r & 255;
        size_t tb = ((size_t)(nb * 8 + ch)) * TILEB_B;
        img_store(g_ABi_h, g_ABi_l, tb, swz((uint32_t)(brow * 128 + lc * 2)), v);
    }
}

__global__ void split_AT_image(const float* __restrict__ A)
{
    int i = blockIdx.x * blockDim.x + threadIdx.x;
    if (i >= Nn * Mm) return;
    int n = i >> 10, k = i & 1023;
    float v = A[(size_t)k * Nn + n];
    int nb = n >> 8, brow = n & 255, ch = k >> 6, lc = k & 63;
    size_t tb = ((size_t)(nb * 16 + ch)) * TILEB_B;
    img_store(g_ATi_h, g_ATi_l, tb, swz((uint32_t)(brow * 128 + lc * 2)), v);
}

__global__ void split_xu_u(const float* __restrict__ x, const float* __restrict__ u)
{
    int i = blockIdx.x * blockDim.x + threadIdx.x;
    if (i >= Bsz * Nn) return;
    int r = i >> 9, k = i & 511;
    int bm = r >> 7, lrow = r & 127, ch = k >> 6, lc = k & 63;
    size_t tb = ((size_t)(bm * 8 + ch)) * TILEA_B;
    uint32_t boff = swz((uint32_t)(lrow * 128 + lc * 2));
    float uv = u[i];
    img_store(g_xu_h, g_xu_l, tb, boff, x[i] + uv);
    img_store(g_u_h,  g_u_l,  tb, boff, uv);
}

// ---------------------------------------------------------------------------
extern "C" void kernel_launch(void* const* d_in, const int* in_sizes, int n_in,
                              void* d_out, int out_size)
{
    const float* x = (const float*)d_in[0];
    const float* u = (const float*)d_in[1];
    const float* A = (const float*)d_in[2];
    const float* b = (const float*)d_in[3];
    float* out = (float*)d_out;

    float *c, *msk, *act, *qdg;
    __nv_bfloat16 *AAh, *AAl, *ABh, *ABl, *ATh, *ATl, *XUh, *XUl, *Uh, *Ul,
                  *Zh, *Zl, *Qh, *Ql, *lAh, *lAl, *lBh, *lBl;
    cudaGetSymbolAddress((void**)&c,   g_c);
    cudaGetSymbolAddress((void**)&msk, g_msk);
    cudaGetSymbolAddress((void**)&act, g_act);
    cudaGetSymbolAddress((void**)&qdg, g_qdiag);
    cudaGetSymbolAddress((void**)&AAh, g_AAi_h); cudaGetSymbolAddress((void**)&AAl, g_AAi_l);
    cudaGetSymbolAddress((void**)&ABh, g_ABi_h); cudaGetSymbolAddress((void**)&ABl, g_ABi_l);
    cudaGetSymbolAddress((void**)&ATh, g_ATi_h); cudaGetSymbolAddress((void**)&ATl, g_ATi_l);
    cudaGetSymbolAddress((void**)&XUh, g_xu_h);  cudaGetSymbolAddress((void**)&XUl, g_xu_l);
    cudaGetSymbolAddress((void**)&Uh,  g_u_h);   cudaGetSymbolAddress((void**)&Ul,  g_u_l);
    cudaGetSymbolAddress((void**)&Zh,  g_z_h);   cudaGetSymbolAddress((void**)&Zl,  g_z_l);
    cudaGetSymbolAddress((void**)&Qh,  g_Qhi);   cudaGetSymbolAddress((void**)&Ql,  g_Qlo);
    cudaGetSymbolAddress((void**)&lAh, g_lAhi);  cudaGetSymbolAddress((void**)&lAl, g_lAlo);
    cudaGetSymbolAddress((void**)&lBh, g_lBhi);  cudaGetSymbolAddress((void**)&lBl, g_lBlo);

    cudaFuncSetAttribute(tc_gemm<E_C>,   cudaFuncAttributeMaxDynamicSharedMemorySize, DSMEM);
    cudaFuncSetAttribute(tc_gemm<E_ACT>, cudaFuncAttributeMaxDynamicSharedMemorySize, DSMEM);
    cudaFuncSetAttribute(tc_gemm<E_MSK>, cudaFuncAttributeMaxDynamicSharedMemorySize, DSMEM);
    cudaFuncSetAttribute(tc_gemm<E_Z>,   cudaFuncAttributeMaxDynamicSharedMemorySize, DSMEM);
    cudaFuncSetAttribute(tc_gemm<E_OUT>, cudaFuncAttributeMaxDynamicSharedMemorySize, DSMEM);
    cudaFuncSetAttribute(tc_gemm<E_Q>,   cudaFuncAttributeMaxDynamicSharedMemorySize, DSMEM);
    cudaFuncSetAttribute(pgd_pdl,        cudaFuncAttributeMaxDynamicSharedMemorySize, DSMEM3);

    const dim3 blk(256);
    const int EW = 256;

    // prep (plain launches — first in chain)
    split_A_images<<<(Mm * Nn + EW - 1) / EW, EW>>>(A);
    split_AT_image<<<(Nn * Mm + EW - 1) / EW, EW>>>(A);
    split_xu_u<<<(int)(((size_t)Bsz * Nn + EW - 1) / EW), EW>>>(x, u);

    // PDL config (grid mutated per launch)
    cudaLaunchAttribute pdlAttr;
    pdlAttr.id = cudaLaunchAttributeProgrammaticStreamSerialization;
    pdlAttr.val.programmaticStreamSerializationAllowed = 1;
    cudaLaunchConfig_t cfg = {};
    cfg.blockDim = blk;
    cfg.dynamicSmemBytes = DSMEM;
    cfg.stream = 0;
    cfg.attrs = &pdlAttr;
    cfg.numAttrs = 1;

    // Q' = A @ A^T - (1/step) I -> 128-row Q B-tiles + diag vector
    cfg.gridDim = dim3(4, 8);
    cudaLaunchKernelEx(&cfg, tc_gemm<E_Q>,
                       (const __nv_bfloat16*)AAh, (const __nv_bfloat16*)AAl,
                       (const __nv_bfloat16*)ABh, (const __nv_bfloat16*)ABl, 8,
                       (const float*)nullptr, (const float*)nullptr,
                       qdg, Qh, Ql, 1024, 0);

    // c = xu @ A^T - b (+ lam init): operands from prep -> early=3
    cfg.gridDim = dim3(4, 32);
    cudaLaunchKernelEx(&cfg, tc_gemm<E_C>,
                       (const __nv_bfloat16*)XUh, (const __nv_bfloat16*)XUl,
                       (const __nv_bfloat16*)ABh, (const __nv_bfloat16*)ABl, 8,
                       (const float*)b, (const float*)nullptr,
                       c, lAh, lAl, 1024, 3);

    // PGD iters 2..50 (49 PDL launches, TM=256 x TN=128)
    cudaLaunchConfig_t cfgP = cfg;
    cfgP.dynamicSmemBytes = DSMEM3;
    cfgP.gridDim = dim3(8, 16);
    __nv_bfloat16 *curh = lAh, *curl = lAl, *nxth = lBh, *nxtl = lBl;
    for (int it = 1; it < 50; it++) {
        cudaLaunchKernelEx(&cfgP, pgd_pdl,
                           (const __nv_bfloat16*)curh, (const __nv_bfloat16*)curl,
                           (const __nv_bfloat16*)Qh,  (const __nv_bfloat16*)Ql,
                           (const float*)c, (const float*)nullptr, (const float*)qdg,
                           nxth, nxtl, 0);
        __nv_bfloat16* t;
        t = curh; curh = nxth; nxth = t;
        t = curl; curl = nxtl; nxtl = t;
    }

    // z = x + u - lam @ A  (A = lam from pred -> earlyB only)
    cfg.gridDim = dim3(2, 32);
    cudaLaunchKernelEx(&cfg, tc_gemm<E_Z>,
                       (const __nv_bfloat16*)curh, (const __nv_bfloat16*)curl,
                       (const __nv_bfloat16*)ATh, (const __nv_bfloat16*)ATl, 16,
                       (const float*)x, (const float*)u,
                       (float*)nullptr, Zh, Zl, 512, 2);
    // active  (A = z from pred -> earlyB only)
    cfg.gridDim = dim3(4, 32);
    cudaLaunchKernelEx(&cfg, tc_gemm<E_ACT>,
                       (const __nv_bfloat16*)Zh, (const __nv_bfloat16*)Zl,
                       (const __nv_bfloat16*)ABh, (const __nv_bfloat16*)ABl, 8,
                       (const float*)b, (const float*)nullptr,
                       act, (__nv_bfloat16*)nullptr, (__nv_bfloat16*)nullptr, 1024, 2);
    // masked (+ masked lam init): both operands prep-constant -> early=3
    cfg.gridDim = dim3(4, 32);
    cudaLaunchKernelEx(&cfg, tc_gemm<E_MSK>,
                       (const __nv_bfloat16*)Uh, (const __nv_bfloat16*)Ul,
                       (const __nv_bfloat16*)ABh, (const __nv_bfloat16*)ABl, 8,
                       (const float*)act, (const float*)nullptr,
                       msk, lAh, lAl, 1024, 3);

    // masked PGD iters 2..10 (9 PDL launches)
    curh = lAh; curl = lAl; nxth = lBh; nxtl = lBl;
    for (int it = 1; it < 10; it++) {
        cudaLaunchKernelEx(&cfgP, pgd_pdl,
                           (const __nv_bfloat16*)curh, (const __nv_bfloat16*)curl,
                           (const __nv_bfloat16*)Qh,  (const __nv_bfloat16*)Ql,
                           (const float*)msk, (const float*)act, (const float*)qdg,
                           nxth, nxtl, 1);
        __nv_bfloat16* t;
        t = curh; curh = nxth; nxth = t;
        t = curl; curl = nxtl; nxtl = t;
    }

    // out = u - lam @ A  (A = lam from pred -> earlyB only)
    cfg.gridDim = dim3(2, 32);
    cudaLaunchKernelEx(&cfg, tc_gemm<E_OUT>,
                       (const __nv_bfloat16*)curh, (const __nv_bfloat16*)curl,
                       (const __nv_bfloat16*)ATh, (const __nv_bfloat16*)ATl, 16,
                       (const float*)u, (const float*)nullptr,
                       out, (__nv_bfloat16*)nullptr, (__nv_bfloat16*)nullptr, 512, 2);
}